// round 8
// baseline (speedup 1.0000x reference)
#include <cuda_runtime.h>

typedef unsigned long long ull;

#define TLEN 4000
#define HID  64
#define NTHR 256

__device__ __forceinline__ void ffma2(ull &d, ull a, ull b) {
    asm("fma.rn.f32x2 %0, %1, %2, %0;" : "+l"(d) : "l"(a), "l"(b));
}
__device__ __forceinline__ float2 unpack2(ull v) {
    float2 r;
    asm("mov.b64 {%0, %1}, %2;" : "=f"(r.x), "=f"(r.y) : "l"(v));
    return r;
}
__device__ __forceinline__ ull pack2(float x, float y) {
    ull r;
    asm("mov.b64 %0, {%1, %2};" : "=l"(r) : "f"(x), "f"(y));
    return r;
}
__device__ __forceinline__ float hsum2(ull a, ull b) {
    ull s;
    asm("add.rn.f32x2 %0, %1, %2;" : "=l"(s) : "l"(a), "l"(b));
    float2 f = unpack2(s);
    return f.x + f.y;
}
__device__ __forceinline__ float tanha(float x) {
    float r;
    asm("tanh.approx.f32 %0, %1;" : "=f"(r) : "f"(x));
    return r;
}
__device__ __forceinline__ float fsigmoid(float x) {
    return fmaf(tanha(0.5f * x), 0.5f, 0.5f);
}

__global__ void __launch_bounds__(NTHR, 1)
lstm2_bp(const float* __restrict__ x,
         const float* __restrict__ W_ih0,
         const float* __restrict__ W_hh0,
         const float* __restrict__ b_ih0,
         const float* __restrict__ b_hh0,
         const float* __restrict__ W_ih1,
         const float* __restrict__ W_hh1,
         const float* __restrict__ b_ih1,
         const float* __restrict__ b_hh1,
         const float* __restrict__ W_fc,
         const float* __restrict__ b_fc,
         float* __restrict__ out)
{
    __shared__ __align__(16) float  sh_x[2 * TLEN];     // 32 KB staged input
    __shared__ __align__(16) float  sh_h[2][2 * HID];   // [batch][h0|h1]
    __shared__ __align__(16) float2 sh_g[2][8][32];     // [batch][warp][lane]={gA,gB}

    const int tid   = threadIdx.x;
    const int w     = tid >> 5;
    const int l     = tid & 31;
    const int j     = l & 7;           // unit-local
    const int q     = l >> 3;          // gate (i,f,g,o)
    const int u     = 8 * w + j;       // unit 0..63
    const int row   = 64 * q + u;      // gate row this thread owns
    const int bbase = blockIdx.x * 2;

    // Stage x (two contiguous batch rows: X=[0,T), Y=[T,2T))
    {
        const float4* xg = (const float4*)(x + (size_t)bbase * TLEN);
        float4* xs = (float4*)sh_x;
        for (int i = tid; i < 2 * TLEN / 4; i += NTHR) xs[i] = xg[i];
    }
    ((float*)sh_h)[tid] = 0.0f;        // 256 floats = both batches' h0,h1

    // Per-thread weight rows in registers (packed f32 pairs).
    ull wA[32], wI[32], wH[32];        // W_hh0 / W_ih1 / W_hh1 row `row`
    {
        const ulonglong2* p = (const ulonglong2*)(W_hh0 + row * HID);
        #pragma unroll
        for (int t = 0; t < 16; t++) { ulonglong2 v = p[t]; wA[2*t] = v.x; wA[2*t+1] = v.y; }
        p = (const ulonglong2*)(W_ih1 + row * HID);
        #pragma unroll
        for (int t = 0; t < 16; t++) { ulonglong2 v = p[t]; wI[2*t] = v.x; wI[2*t+1] = v.y; }
        p = (const ulonglong2*)(W_hh1 + row * HID);
        #pragma unroll
        for (int t = 0; t < 16; t++) { ulonglong2 v = p[t]; wH[2*t] = v.x; wH[2*t+1] = v.y; }
    }
    const float wx    = W_ih0[row];
    const float biasA = b_ih0[row] + b_hh0[row];
    const float biasB = b_ih1[row] + b_hh1[row];

    // Pointwise: lanes q<2 own item (layer L=q, unit u) for BOTH batches.
    const bool pwact = (q < 2);
    const int  L     = q & 1;
    const int  gidx  = 2 * j + L;      // float index into warp gate scratch
    const float* gX = (const float*)&sh_g[0][w][0];
    const float* gY = (const float*)&sh_g[1][w][0];
    float cX = 0.0f, cY = 0.0f;

    __syncthreads();

    // Half A of iter m: pointwise Y (gates from half B of m-1) + matvec X(m).
    // Half B of iter m: pointwise X (gates from half A of m)   + matvec Y(m).
    // matvec(m) computes gA(m) [layer0] and gB(m-1) [layer1].
    for (int m = 0; m <= TLEN + 1; ++m) {
        // ---------- half A ----------
        if (pwact) {   // pw Y: layer0 -> h0Y(m-1), layer1 -> h1Y(m-2)
            float gi = gY[gidx], gf = gY[gidx + 16];
            float gc = gY[gidx + 32], go = gY[gidx + 48];
            float iv = fsigmoid(gi), fv = fsigmoid(gf), ov = fsigmoid(go);
            float cv = tanha(gc);
            float cn = fmaf(fv, cY, iv * cv);
            bool act = L ? (m >= 2) : (m >= 1 && m <= TLEN);
            if (act) { cY = cn; sh_h[1][L * HID + u] = ov * tanha(cY); }
        }
        if (m <= TLEN) {   // mv X(m): reads h0X(m-1), h1X(m-2)
            const int xk = (m < TLEN) ? m : TLEN - 1;
            ull aA = pack2(fmaf(sh_x[xk], wx, biasA), 0.0f), aA2 = 0ull;
            ull aB = pack2(biasB, 0.0f),                     aB2 = 0ull;
            const ulonglong2* h0 = (const ulonglong2*)&sh_h[0][0];
            const ulonglong2* h1 = (const ulonglong2*)&sh_h[0][HID];
            #pragma unroll
            for (int t = 0; t < 16; t++) {
                ulonglong2 v = h0[t];
                ffma2(aA, wA[2*t],   v.x);
                ffma2(aB, wI[2*t],   v.x);
                ffma2(aA2, wA[2*t+1], v.y);
                ffma2(aB2, wI[2*t+1], v.y);
            }
            #pragma unroll
            for (int t = 0; t < 16; t++) {
                ulonglong2 v = h1[t];
                ffma2(aB,  wH[2*t],   v.x);
                ffma2(aB2, wH[2*t+1], v.y);
            }
            sh_g[0][w][l] = make_float2(hsum2(aA, aA2), hsum2(aB, aB2));
        }
        __syncthreads();
        if (m == TLEN + 1) break;
        // ---------- half B ----------
        if (pwact) {   // pw X: layer0 -> h0X(m), layer1 -> h1X(m-1)
            float gi = gX[gidx], gf = gX[gidx + 16];
            float gc = gX[gidx + 32], go = gX[gidx + 48];
            float iv = fsigmoid(gi), fv = fsigmoid(gf), ov = fsigmoid(go);
            float cv = tanha(gc);
            float cn = fmaf(fv, cX, iv * cv);
            bool act = L ? (m >= 1) : (m <= TLEN - 1);
            if (act) { cX = cn; sh_h[0][L * HID + u] = ov * tanha(cX); }
        }
        if (m <= TLEN) {   // mv Y(m): reads h0Y(m-1), h1Y(m-2)
            const int xk = (m < TLEN) ? m : TLEN - 1;
            ull aA = pack2(fmaf(sh_x[TLEN + xk], wx, biasA), 0.0f), aA2 = 0ull;
            ull aB = pack2(biasB, 0.0f),                            aB2 = 0ull;
            const ulonglong2* h0 = (const ulonglong2*)&sh_h[1][0];
            const ulonglong2* h1 = (const ulonglong2*)&sh_h[1][HID];
            #pragma unroll
            for (int t = 0; t < 16; t++) {
                ulonglong2 v = h0[t];
                ffma2(aA, wA[2*t],   v.x);
                ffma2(aB, wI[2*t],   v.x);
                ffma2(aA2, wA[2*t+1], v.y);
                ffma2(aB2, wI[2*t+1], v.y);
            }
            #pragma unroll
            for (int t = 0; t < 16; t++) {
                ulonglong2 v = h1[t];
                ffma2(aB,  wH[2*t],   v.x);
                ffma2(aB2, wH[2*t+1], v.y);
            }
            sh_g[1][w][l] = make_float2(hsum2(aA, aA2), hsum2(aB, aB2));
        }
        __syncthreads();
    }

    // ---- FC head on final h1 of both batches ----
    {
        const int e  = tid & 127;
        const int bb = tid >> 7;
        float acc = b_fc[e];
        const float* wr = W_fc + e * HID;
        const float* hv = &sh_h[bb][HID];
        #pragma unroll
        for (int t = 0; t < HID; t += 4) {
            acc = fmaf(wr[t],     hv[t],     acc);
            acc = fmaf(wr[t + 1], hv[t + 1], acc);
            acc = fmaf(wr[t + 2], hv[t + 2], acc);
            acc = fmaf(wr[t + 3], hv[t + 3], acc);
        }
        out[(size_t)(bbase + bb) * 128 + e] = acc;
    }
}

extern "C" void kernel_launch(void* const* d_in, const int* in_sizes, int n_in,
                              void* d_out, int out_size) {
    (void)in_sizes; (void)n_in; (void)out_size;
    lstm2_bp<<<128, NTHR>>>(
        (const float*)d_in[0],   // x
        (const float*)d_in[1],   // W_ih0
        (const float*)d_in[2],   // W_hh0
        (const float*)d_in[3],   // b_ih0
        (const float*)d_in[4],   // b_hh0
        (const float*)d_in[5],   // W_ih1
        (const float*)d_in[6],   // W_hh1
        (const float*)d_in[7],   // b_ih1
        (const float*)d_in[8],   // b_hh1
        (const float*)d_in[9],   // W_fc
        (const float*)d_in[10],  // b_fc
        (float*)d_out);
}

// round 9
// speedup vs baseline: 1.9608x; 1.9608x over previous
#include <cuda_runtime.h>

typedef unsigned long long ull;

#define TLEN 4000
#define HID  64
#define NTHR 256

__device__ __forceinline__ void ffma2(ull &d, ull a, ull b) {
    asm("fma.rn.f32x2 %0, %1, %2, %0;" : "+l"(d) : "l"(a), "l"(b));
}
__device__ __forceinline__ float2 unpack2(ull v) {
    float2 r;
    asm("mov.b64 {%0, %1}, %2;" : "=f"(r.x), "=f"(r.y) : "l"(v));
    return r;
}
__device__ __forceinline__ ull pack2(float x, float y) {
    ull r;
    asm("mov.b64 %0, {%1, %2};" : "=l"(r) : "f"(x), "f"(y));
    return r;
}
__device__ __forceinline__ float hsum2(ull a, ull b) {
    ull s;
    asm("add.rn.f32x2 %0, %1, %2;" : "=l"(s) : "l"(a), "l"(b));
    float2 f = unpack2(s);
    return f.x + f.y;
}
__device__ __forceinline__ float tanha(float x) {
    float r;
    asm("tanh.approx.f32 %0, %1;" : "=f"(r) : "f"(x));
    return r;
}
__device__ __forceinline__ float fsigmoid(float x) {
    return fmaf(tanha(0.5f * x), 0.5f, 0.5f);
}

__global__ void __launch_bounds__(NTHR, 1)
lstm2_ov(const float* __restrict__ x,
         const float* __restrict__ W_ih0,
         const float* __restrict__ W_hh0,
         const float* __restrict__ b_ih0,
         const float* __restrict__ b_hh0,
         const float* __restrict__ W_ih1,
         const float* __restrict__ W_hh1,
         const float* __restrict__ b_ih1,
         const float* __restrict__ b_hh1,
         const float* __restrict__ W_fc,
         const float* __restrict__ b_fc,
         float* __restrict__ out)
{
    __shared__ __align__(16) float  sh_x[2 * TLEN];       // 32 KB staged input
    __shared__ __align__(16) float  sh_h[2][2][2 * HID];  // [slot][batch][h0|h1]
    __shared__ __align__(16) float2 sh_sA[8][32];         // layer0 gates {b0,b1}
    __shared__ __align__(16) float2 sh_sB[8][32];         // layer1 gates {b0,b1}

    const int tid   = threadIdx.x;
    const int w     = tid >> 5;
    const int l     = tid & 31;
    const int j     = l & 7;          // unit-local
    const int q     = l >> 3;         // gate index (i,f,g,o) AND pointwise combo
    const int u     = 8 * w + j;      // unit 0..63
    const int row   = 64 * q + u;     // gate row this thread owns
    const int bbase = blockIdx.x * 2;

    // Stage x (two contiguous batch rows)
    {
        const float4* xg = (const float4*)(x + (size_t)bbase * TLEN);
        float4* xs = (float4*)sh_x;
        for (int i = tid; i < 2 * TLEN / 4; i += NTHR) xs[i] = xg[i];
    }
    ((float2*)sh_h)[tid] = make_float2(0.0f, 0.0f);   // zero both slots

    // Per-thread weight rows in registers (packed f32 pairs).
    ull wA[32], wI[32], wH[32];   // W_hh0 / W_ih1 / W_hh1 row `row`
    {
        const ulonglong2* p = (const ulonglong2*)(W_hh0 + row * HID);
        #pragma unroll
        for (int t = 0; t < 16; t++) { ulonglong2 v = p[t]; wA[2*t] = v.x; wA[2*t+1] = v.y; }
        p = (const ulonglong2*)(W_ih1 + row * HID);
        #pragma unroll
        for (int t = 0; t < 16; t++) { ulonglong2 v = p[t]; wI[2*t] = v.x; wI[2*t+1] = v.y; }
        p = (const ulonglong2*)(W_hh1 + row * HID);
        #pragma unroll
        for (int t = 0; t < 16; t++) { ulonglong2 v = p[t]; wH[2*t] = v.x; wH[2*t+1] = v.y; }
    }
    const float wx    = W_ih0[row];
    const float biasA = b_ih0[row] + b_hh0[row];
    const float biasB = b_ih1[row] + b_hh1[row];

    // Pointwise combo for this lane: q -> (layer Lq = q>>1, batch bq = q&1), unit u.
    const int Lq = q >> 1;
    const int bq = q & 1;
    const int hoff = Lq * HID + u;
    float c = 0.0f;

    __syncthreads();

    // Iter k: gA(k) [layer0 step k] + gB(k-1) [layer1 step k-1].
    // pw0 (layer0) overlaps the wH FFMA2 block; only pw1 is exposed.
    // ONE CTA barrier per step.
    for (int k = 0; k <= TLEN; ++k) {
        const int rs = (k + 1) & 1;   // slot holding h0(k-1), h1(k-2)
        const int ws = k & 1;         // slot receiving h0(k), h1(k-1)

        const ulonglong2* h0b0 = (const ulonglong2*)&sh_h[rs][0][0];
        const ulonglong2* h0b1 = (const ulonglong2*)&sh_h[rs][1][0];
        const ulonglong2* h1b0 = (const ulonglong2*)&sh_h[rs][0][HID];
        const ulonglong2* h1b1 = (const ulonglong2*)&sh_h[rs][1][HID];

        // ---- phase 1: shared-h0 loop -> completes gA, starts gB ----
        const int xk = (k < TLEN) ? k : TLEN - 1;
        ull aA0x = pack2(fmaf(sh_x[xk], wx, biasA), 0.0f),        aA0y = 0ull;
        ull aA1x = pack2(fmaf(sh_x[TLEN + xk], wx, biasA), 0.0f), aA1y = 0ull;
        ull aB0x = pack2(biasB, 0.0f), aB0y = 0ull;
        ull aB1x = aB0x,               aB1y = 0ull;
        #pragma unroll
        for (int t = 0; t < 16; t++) {
            ulonglong2 v0 = h0b0[t], v1 = h0b1[t];
            ffma2(aA0x, wA[2*t],   v0.x);
            ffma2(aA1x, wA[2*t],   v1.x);
            ffma2(aB0x, wI[2*t],   v0.x);
            ffma2(aB1x, wI[2*t],   v1.x);
            ffma2(aA0y, wA[2*t+1], v0.y);
            ffma2(aA1y, wA[2*t+1], v1.y);
            ffma2(aB0y, wI[2*t+1], v0.y);
            ffma2(aB1y, wI[2*t+1], v1.y);
        }
        sh_sA[w][l] = make_float2(hsum2(aA0x, aA0y), hsum2(aA1x, aA1y));
        __syncwarp();

        // ---- phase 2: wH FFMA2 block, with pw0 chain overlapped ----
        #pragma unroll
        for (int t = 0; t < 16; t++) {
            ulonglong2 v0 = h1b0[t], v1 = h1b1[t];
            ffma2(aB0x, wH[2*t],   v0.x);
            ffma2(aB1x, wH[2*t],   v1.x);
            ffma2(aB0y, wH[2*t+1], v0.y);
            ffma2(aB1y, wH[2*t+1], v1.y);
        }
        if (q < 2) {   // pw0: layer0, combo (batch bq, unit u) -- hides under wH
            float gi = (bq ? sh_sA[w][j     ].y : sh_sA[w][j     ].x);
            float gf = (bq ? sh_sA[w][j +  8].y : sh_sA[w][j +  8].x);
            float gc = (bq ? sh_sA[w][j + 16].y : sh_sA[w][j + 16].x);
            float go = (bq ? sh_sA[w][j + 24].y : sh_sA[w][j + 24].x);
            float iv = fsigmoid(gi), fv = fsigmoid(gf), ov = fsigmoid(go);
            float cv = tanha(gc);
            float cn = fmaf(fv, c, iv * cv);
            if (k < TLEN) {
                c = cn;
                sh_h[ws][bq][hoff] = ov * tanha(c);   // h0(k)
            }
        }
        sh_sB[w][l] = make_float2(hsum2(aB0x, aB0y), hsum2(aB1x, aB1y));
        __syncwarp();

        // ---- phase 3: pw1 (layer1) -- exposed tail ----
        if (q >= 2) {
            float gi = (bq ? sh_sB[w][j     ].y : sh_sB[w][j     ].x);
            float gf = (bq ? sh_sB[w][j +  8].y : sh_sB[w][j +  8].x);
            float gc = (bq ? sh_sB[w][j + 16].y : sh_sB[w][j + 16].x);
            float go = (bq ? sh_sB[w][j + 24].y : sh_sB[w][j + 24].x);
            float iv = fsigmoid(gi), fv = fsigmoid(gf), ov = fsigmoid(go);
            float cv = tanha(gc);
            float cn = fmaf(fv, c, iv * cv);
            if (k >= 1) {
                c = cn;
                sh_h[ws][bq][hoff] = ov * tanha(c);   // h1(k-1)
            }
        }
        __syncthreads();
    }

    // ---- FC head on final h1 (h1(3999) written at k=4000 -> slot 0) ----
    {
        const int e  = tid & 127;
        const int bb = tid >> 7;
        float acc = b_fc[e];
        const float* wr = W_fc + e * HID;
        const float* hv = &sh_h[0][bb][HID];
        #pragma unroll
        for (int t = 0; t < HID; t += 4) {
            acc = fmaf(wr[t],     hv[t],     acc);
            acc = fmaf(wr[t + 1], hv[t + 1], acc);
            acc = fmaf(wr[t + 2], hv[t + 2], acc);
            acc = fmaf(wr[t + 3], hv[t + 3], acc);
        }
        out[(size_t)(bbase + bb) * 128 + e] = acc;
    }
}

extern "C" void kernel_launch(void* const* d_in, const int* in_sizes, int n_in,
                              void* d_out, int out_size) {
    (void)in_sizes; (void)n_in; (void)out_size;
    lstm2_ov<<<128, NTHR>>>(
        (const float*)d_in[0],   // x
        (const float*)d_in[1],   // W_ih0
        (const float*)d_in[2],   // W_hh0
        (const float*)d_in[3],   // b_ih0
        (const float*)d_in[4],   // b_hh0
        (const float*)d_in[5],   // W_ih1
        (const float*)d_in[6],   // W_hh1
        (const float*)d_in[7],   // b_ih1
        (const float*)d_in[8],   // b_hh1
        (const float*)d_in[9],   // W_fc
        (const float*)d_in[10],  // b_fc
        (float*)d_out);
}

// round 10
// speedup vs baseline: 2.2778x; 1.1617x over previous
#include <cuda_runtime.h>

typedef unsigned long long ull;

#define TLEN 4000
#define HID  64
#define NTHR 256

__device__ __forceinline__ void ffma2(ull &d, ull a, ull b) {
    asm("fma.rn.f32x2 %0, %1, %2, %0;" : "+l"(d) : "l"(a), "l"(b));
}
__device__ __forceinline__ float2 unpack2(ull v) {
    float2 r;
    asm("mov.b64 {%0, %1}, %2;" : "=f"(r.x), "=f"(r.y) : "l"(v));
    return r;
}
__device__ __forceinline__ ull pack2(float x, float y) {
    ull r;
    asm("mov.b64 %0, {%1, %2};" : "=l"(r) : "f"(x), "f"(y));
    return r;
}
__device__ __forceinline__ float hsum2(ull a, ull b) {
    ull s;
    asm("add.rn.f32x2 %0, %1, %2;" : "=l"(s) : "l"(a), "l"(b));
    float2 f = unpack2(s);
    return f.x + f.y;
}
__device__ __forceinline__ float tanha(float x) {
    float r;
    asm("tanh.approx.f32 %0, %1;" : "=f"(r) : "f"(x));
    return r;
}
__device__ __forceinline__ float fsigmoid(float x) {
    return fmaf(tanha(0.5f * x), 0.5f, 0.5f);
}

__global__ void __launch_bounds__(NTHR, 1)
lstm2_r10(const float* __restrict__ x,
          const float* __restrict__ W_ih0,
          const float* __restrict__ W_hh0,
          const float* __restrict__ b_ih0,
          const float* __restrict__ b_hh0,
          const float* __restrict__ W_ih1,
          const float* __restrict__ W_hh1,
          const float* __restrict__ b_ih1,
          const float* __restrict__ b_hh1,
          const float* __restrict__ W_fc,
          const float* __restrict__ b_fc,
          float* __restrict__ out)
{
    __shared__ __align__(16) float  sh_x[2 * TLEN];       // 32 KB staged input
    __shared__ __align__(16) float  sh_h[2][2][2 * HID];  // [slot][batch][h0|h1]
    __shared__ __align__(16) float2 sh_sA[8][32];         // layer0 gates {b0,b1}
    __shared__ __align__(16) float2 sh_pad[8];            // bank shift for sh_sB
    __shared__ __align__(16) float2 sh_sB[8][32];         // layer1 gates {b0,b1}

    const int tid   = threadIdx.x;
    const int w     = tid >> 5;
    const int l     = tid & 31;
    const int j     = l & 7;          // unit-local
    const int q     = l >> 3;         // gate index AND pointwise combo
    const int u     = 8 * w + j;      // unit 0..63
    const int row   = 64 * q + u;     // gate row this thread owns
    const int bbase = blockIdx.x * 2;

    (void)sh_pad;

    // Stage x (two contiguous batch rows)
    {
        const float4* xg = (const float4*)(x + (size_t)bbase * TLEN);
        float4* xs = (float4*)sh_x;
        for (int i = tid; i < 2 * TLEN / 4; i += NTHR) xs[i] = xg[i];
    }
    ((float2*)sh_h)[tid] = make_float2(0.0f, 0.0f);   // zero both slots

    // Per-thread weight rows in registers (packed f32 pairs).
    ull wA[32], wI[32], wH[32];   // W_hh0 / W_ih1 / W_hh1 row `row`
    {
        const ulonglong2* p = (const ulonglong2*)(W_hh0 + row * HID);
        #pragma unroll
        for (int t = 0; t < 16; t++) { ulonglong2 v = p[t]; wA[2*t] = v.x; wA[2*t+1] = v.y; }
        p = (const ulonglong2*)(W_ih1 + row * HID);
        #pragma unroll
        for (int t = 0; t < 16; t++) { ulonglong2 v = p[t]; wI[2*t] = v.x; wI[2*t+1] = v.y; }
        p = (const ulonglong2*)(W_hh1 + row * HID);
        #pragma unroll
        for (int t = 0; t < 16; t++) { ulonglong2 v = p[t]; wH[2*t] = v.x; wH[2*t+1] = v.y; }
    }
    const float wx    = W_ih0[row];
    const float biasA = b_ih0[row] + b_hh0[row];
    const float biasB = b_ih1[row] + b_hh1[row];

    // Pointwise combo: q -> (layer Lq = q>>1, batch bq = q&1), unit u.
    const int Lq = q >> 1;
    const int bq = q & 1;
    const int hoff = Lq * HID + u;
    // Fixed per-thread gate-read pointer (layer selects array) + indices.
    const float* gp = Lq ? (const float*)&sh_sB[w][0] : (const float*)&sh_sA[w][0];
    const int gi0 = (j     ) * 2 + bq;
    const int gi1 = (j +  8) * 2 + bq;
    const int gi2 = (j + 16) * 2 + bq;
    const int gi3 = (j + 24) * 2 + bq;
    float c = 0.0f;

    __syncthreads();

    // ---- peel k=0: gates are pure bias (+x term); layer0 pointwise only ----
    {
        sh_sA[w][l] = make_float2(fmaf(sh_x[0],    wx, biasA),
                                  fmaf(sh_x[TLEN], wx, biasA));
        __syncwarp();
        if (q < 2) {
            float g_i = gp[gi0], g_f = gp[gi1], g_c = gp[gi2], g_o = gp[gi3];
            float iv = fsigmoid(g_i), fv = fsigmoid(g_f), ov = fsigmoid(g_o);
            float cv = tanha(g_c);
            c = fmaf(fv, c, iv * cv);
            sh_h[0][bq][hoff] = ov * tanha(c);    // h0(0) -> slot 0
        }
        __syncthreads();
    }

    // ---- main loop k = 1 .. TLEN-1: guard-free ----
    for (int k = 1; k < TLEN; ++k) {
        const int rs = (k + 1) & 1;   // slot holding h0(k-1), h1(k-2)
        const int ws = k & 1;         // slot receiving h0(k), h1(k-1)

        const ulonglong2* h0b0 = (const ulonglong2*)&sh_h[rs][0][0];
        const ulonglong2* h0b1 = (const ulonglong2*)&sh_h[rs][1][0];
        const ulonglong2* h1b0 = (const ulonglong2*)&sh_h[rs][0][HID];
        const ulonglong2* h1b1 = (const ulonglong2*)&sh_h[rs][1][HID];

        // h0 loop: wA (layer0) + wI (layer1-ih), shared h0 loads
        ull aA0x = pack2(fmaf(sh_x[k], wx, biasA), 0.0f),        aA0y = 0ull;
        ull aA1x = pack2(fmaf(sh_x[TLEN + k], wx, biasA), 0.0f), aA1y = 0ull;
        ull aB0x = pack2(biasB, 0.0f), aB0y = 0ull;
        ull aB1x = aB0x,               aB1y = 0ull;
        #pragma unroll
        for (int t = 0; t < 16; t++) {
            ulonglong2 v0 = h0b0[t], v1 = h0b1[t];
            ffma2(aA0x, wA[2*t],   v0.x);
            ffma2(aA1x, wA[2*t],   v1.x);
            ffma2(aB0x, wI[2*t],   v0.x);
            ffma2(aB1x, wI[2*t],   v1.x);
            ffma2(aA0y, wA[2*t+1], v0.y);
            ffma2(aA1y, wA[2*t+1], v1.y);
            ffma2(aB0y, wI[2*t+1], v0.y);
            ffma2(aB1y, wI[2*t+1], v1.y);
        }
        sh_sA[w][l] = make_float2(hsum2(aA0x, aA0y), hsum2(aA1x, aA1y));
        __syncwarp();

        // h1 loop: wH (layer1-hh)
        #pragma unroll
        for (int t = 0; t < 16; t++) {
            ulonglong2 v0 = h1b0[t], v1 = h1b1[t];
            ffma2(aB0x, wH[2*t],   v0.x);
            ffma2(aB1x, wH[2*t],   v1.x);
            ffma2(aB0y, wH[2*t+1], v0.y);
            ffma2(aB1y, wH[2*t+1], v1.y);
        }
        sh_sB[w][l] = make_float2(hsum2(aB0x, aB0y), hsum2(aB1x, aB1y));
        __syncwarp();

        // pointwise: branch-free, one combo per lane
        {
            float g_i = gp[gi0], g_f = gp[gi1], g_c = gp[gi2], g_o = gp[gi3];
            float iv = fsigmoid(g_i), fv = fsigmoid(g_f), ov = fsigmoid(g_o);
            float cv = tanha(g_c);
            c = fmaf(fv, c, iv * cv);
            sh_h[ws][bq][hoff] = ov * tanha(c);   // h0(k) / h1(k-1)
        }
        __syncthreads();
    }

    // ---- tail: gB(TLEN-1) only, then layer1 pointwise -> h1(TLEN-1) ----
    {
        // reads h0(TLEN-1), h1(TLEN-2) -- both in slot (TLEN-1)&1 = 1
        const ulonglong2* h0b0 = (const ulonglong2*)&sh_h[1][0][0];
        const ulonglong2* h0b1 = (const ulonglong2*)&sh_h[1][1][0];
        const ulonglong2* h1b0 = (const ulonglong2*)&sh_h[1][0][HID];
        const ulonglong2* h1b1 = (const ulonglong2*)&sh_h[1][1][HID];
        ull aB0x = pack2(biasB, 0.0f), aB0y = 0ull;
        ull aB1x = aB0x,               aB1y = 0ull;
        #pragma unroll
        for (int t = 0; t < 16; t++) {
            ulonglong2 v0 = h0b0[t], v1 = h0b1[t];
            ffma2(aB0x, wI[2*t],   v0.x);
            ffma2(aB1x, wI[2*t],   v1.x);
            ffma2(aB0y, wI[2*t+1], v0.y);
            ffma2(aB1y, wI[2*t+1], v1.y);
        }
        #pragma unroll
        for (int t = 0; t < 16; t++) {
            ulonglong2 v0 = h1b0[t], v1 = h1b1[t];
            ffma2(aB0x, wH[2*t],   v0.x);
            ffma2(aB1x, wH[2*t],   v1.x);
            ffma2(aB0y, wH[2*t+1], v0.y);
            ffma2(aB1y, wH[2*t+1], v1.y);
        }
        sh_sB[w][l] = make_float2(hsum2(aB0x, aB0y), hsum2(aB1x, aB1y));
        __syncwarp();
        if (q >= 2) {
            float g_i = gp[gi0], g_f = gp[gi1], g_c = gp[gi2], g_o = gp[gi3];
            float iv = fsigmoid(g_i), fv = fsigmoid(g_f), ov = fsigmoid(g_o);
            float cv = tanha(g_c);
            c = fmaf(fv, c, iv * cv);
            sh_h[0][bq][HID + u] = ov * tanha(c);   // h1(TLEN-1) -> slot 0
        }
        __syncthreads();
    }

    // ---- FC head on final h1 (slot 0) ----
    {
        const int e  = tid & 127;
        const int bb = tid >> 7;
        float acc = b_fc[e];
        const float* wr = W_fc + e * HID;
        const float* hv = &sh_h[0][bb][HID];
        #pragma unroll
        for (int t = 0; t < HID; t += 4) {
            acc = fmaf(wr[t],     hv[t],     acc);
            acc = fmaf(wr[t + 1], hv[t + 1], acc);
            acc = fmaf(wr[t + 2], hv[t + 2], acc);
            acc = fmaf(wr[t + 3], hv[t + 3], acc);
        }
        out[(size_t)(bbase + bb) * 128 + e] = acc;
    }
}

extern "C" void kernel_launch(void* const* d_in, const int* in_sizes, int n_in,
                              void* d_out, int out_size) {
    (void)in_sizes; (void)n_in; (void)out_size;
    lstm2_r10<<<128, NTHR>>>(
        (const float*)d_in[0],   // x
        (const float*)d_in[1],   // W_ih0
        (const float*)d_in[2],   // W_hh0
        (const float*)d_in[3],   // b_ih0
        (const float*)d_in[4],   // b_hh0
        (const float*)d_in[5],   // W_ih1
        (const float*)d_in[6],   // W_hh1
        (const float*)d_in[7],   // b_ih1
        (const float*)d_in[8],   // b_hh1
        (const float*)d_in[9],   // W_fc
        (const float*)d_in[10],  // b_fc
        (float*)d_out);
}